// round 13
// baseline (speedup 1.0000x reference)
#include <cuda_runtime.h>
#include <cuda_bf16.h>
#include <math.h>
#include <float.h>
#include <stdint.h>

#define NPTS 4096
#define FIN  6
#define CH   1000
#define KPAD 1024
#define KNN  40
#define NRB  20
#define SCC  205

// ---------------- scratch (device globals; zero-init at module load) ----------------
__device__ float g_adj[(size_t)NPTS * NPTS];      // holds d^2
__device__ float g_sq[NPTS];
__device__ int   g_kidx[NPTS * KNN];
__device__ float g_kval[NPTS * KNN];
__device__ float g_deg[NPTS];
__device__ float g_lval[NPTS * KNN];
__device__ float g_o1[(size_t)NPTS * CH];
__device__ float g_ta[(size_t)NPTS * CH];
__device__ float g_tb[(size_t)NPTS * CH];
__device__ float g_accb[(size_t)NPTS * CH];
__device__ float g_t1a[NPTS * FIN];
__device__ float g_t2a[NPTS * FIN];
__device__ float g_xh1[NPTS * 3 * FIN];
__device__ float g_l2x[NPTS * FIN];
__device__ float g_Mb[CH * FIN];
__device__ float g_vfr[NRB * CH];
__device__ float g_xhr[NRB * 3 * CH];
__device__ float g_reeb[NRB * CH];
__device__ float g_of[2 * CH];
__device__ float g_fc1[512];
__device__ float g_fc2[128];
__device__ float g_part[32 * CH * FIN];           // split-K partials scratch
// bf16 operands (pads beyond col 999 / row 999 never written -> stay zero)
__device__ __nv_bfloat16 g_tbf[(size_t)6 * NPTS * KPAD];   // T0..T5 hi
__device__ __nv_bfloat16 g_o1l[(size_t)NPTS * KPAD];       // o1 lo residual
__device__ __nv_bfloat16 g_w2t[(size_t)6 * KPAD * KPAD];   // W2_k^T [n][k]

// ---------------- bf16 tensor-core GEMM (mma.sync.m16n8k16) ----------------
__device__ __forceinline__ void mma_bf16(float* c, const uint32_t* a, const uint32_t* b) {
    asm volatile(
        "mma.sync.aligned.m16n8k16.row.col.f32.bf16.bf16.f32 "
        "{%0,%1,%2,%3}, {%4,%5,%6,%7}, {%8,%9}, {%0,%1,%2,%3};\n"
        : "+f"(c[0]), "+f"(c[1]), "+f"(c[2]), "+f"(c[3])
        : "r"(a[0]), "r"(a[1]), "r"(a[2]), "r"(a[3]), "r"(b[0]), "r"(b[1]));
}

struct BfSegs {
    const __nv_bfloat16* a[6];
    const __nv_bfloat16* b[6];
};

// KIND 0: cheb  (out = relu(acc + aux[col]))
// KIND 1: adj   (out = max(aux[row]+aux[col]-2*acc, 0) = d^2; lower-tri blocks, mirrored)
// Block 128x128xK, 256 threads, 8 warps (2x4 of 64x32), BK=64, double-buffered smem.
// __launch_bounds__(256, 2): 2 CTAs/SM (2x73728B smem fits carveout) to hide stage-
// boundary sync bubbles and wave-transition idle SMs.
template <int KIND>
__global__ __launch_bounds__(256, 2)
void bfmma_k(BfSegs segs, int nseg, int lda, int ldb,
             const float* __restrict__ aux, float* __restrict__ out, int ldo, int ncap) {
    extern __shared__ __nv_bfloat16 dynsm[];          // [2][128][72] A then [2][128][72] B
    __nv_bfloat16* As = dynsm;
    __nv_bfloat16* Bs = dynsm + 2 * 128 * 72;
    const int tid = threadIdx.x, lane = tid & 31, warp = tid >> 5;
    const int wm0 = (warp & 1) * 64, wn0 = (warp >> 1) * 32;
    const int m0 = blockIdx.y * 128, n0 = blockIdx.x * 128;
    if (KIND == 1 && blockIdx.x > blockIdx.y) return;

    float acc[4][4][4];
#pragma unroll
    for (int i = 0; i < 4; i++)
#pragma unroll
        for (int j = 0; j < 4; j++)
#pragma unroll
            for (int q = 0; q < 4; q++) acc[i][j][q] = 0.f;

    const int lrow = tid >> 1, lko = (tid & 1) * 32;
    uint4 Ar[4], Br[4];
    const int ntiles = nseg * 16;

    {   // prologue: tile 0 -> buf 0
        const uint4* pa = (const uint4*)(segs.a[0] + (size_t)(m0 + lrow) * lda + lko);
        const uint4* pb = (const uint4*)(segs.b[0] + (size_t)(n0 + lrow) * ldb + lko);
#pragma unroll
        for (int j = 0; j < 4; j++) { Ar[j] = pa[j]; Br[j] = pb[j]; }
        uint4* da = (uint4*)&As[(size_t)lrow * 72 + lko];
        uint4* db = (uint4*)&Bs[(size_t)lrow * 72 + lko];
#pragma unroll
        for (int j = 0; j < 4; j++) { da[j] = Ar[j]; db[j] = Br[j]; }
    }
    __syncthreads();

    for (int t = 0; t < ntiles; t++) {
        const int bufe = (t & 1) ? (128 * 72) : 0;    // element offset of current buffer
        if (t + 1 < ntiles) {
            int s = t + 1;
            int seg = s >> 4, kw = (s & 15) * 64;
            const uint4* pa = (const uint4*)(segs.a[seg] + (size_t)(m0 + lrow) * lda + kw + lko);
            const uint4* pb = (const uint4*)(segs.b[seg] + (size_t)(n0 + lrow) * ldb + kw + lko);
#pragma unroll
            for (int j = 0; j < 4; j++) { Ar[j] = pa[j]; Br[j] = pb[j]; }
        }
        const __nv_bfloat16* Ab = As + bufe;
        const __nv_bfloat16* Bb = Bs + bufe;
        const int gr = lane >> 2, gc = lane & 3;
#pragma unroll
        for (int kk = 0; kk < 64; kk += 16) {
            uint32_t au[4][4], bu[4][2];
#pragma unroll
            for (int mi = 0; mi < 4; mi++) {
                int r = wm0 + mi * 16 + gr;
                au[mi][0] = *(const uint32_t*)&Ab[r * 72 + kk + gc * 2];
                au[mi][1] = *(const uint32_t*)&Ab[(r + 8) * 72 + kk + gc * 2];
                au[mi][2] = *(const uint32_t*)&Ab[r * 72 + kk + 8 + gc * 2];
                au[mi][3] = *(const uint32_t*)&Ab[(r + 8) * 72 + kk + 8 + gc * 2];
            }
#pragma unroll
            for (int ni = 0; ni < 4; ni++) {
                int n = wn0 + ni * 8 + gr;
                bu[ni][0] = *(const uint32_t*)&Bb[n * 72 + kk + gc * 2];
                bu[ni][1] = *(const uint32_t*)&Bb[n * 72 + kk + 8 + gc * 2];
            }
#pragma unroll
            for (int mi = 0; mi < 4; mi++)
#pragma unroll
                for (int ni = 0; ni < 4; ni++) mma_bf16(acc[mi][ni], au[mi], bu[ni]);
        }
        if (t + 1 < ntiles) {
            const int nbuf = ((t + 1) & 1) ? (128 * 72) : 0;
            uint4* da = (uint4*)&As[nbuf + (size_t)lrow * 72 + lko];
            uint4* db = (uint4*)&Bs[nbuf + (size_t)lrow * 72 + lko];
#pragma unroll
            for (int j = 0; j < 4; j++) { da[j] = Ar[j]; db[j] = Br[j]; }
            __syncthreads();
        }
    }

    const int gr = lane >> 2, gc2 = (lane & 3) * 2;
#pragma unroll
    for (int mi = 0; mi < 4; mi++) {
#pragma unroll
        for (int ni = 0; ni < 4; ni++) {
#pragma unroll
            for (int q = 0; q < 4; q++) {
                int row = m0 + wm0 + mi * 16 + gr + ((q >= 2) ? 8 : 0);
                int col = n0 + wn0 + ni * 8 + gc2 + (q & 1);
                float v = acc[mi][ni][q];
                if (KIND == 0) {
                    if (col < ncap)
                        out[(size_t)row * ldo + col] = fmaxf(v + aux[col], 0.f);
                } else {
                    float d = fmaxf(aux[row] + aux[col] - 2.f * v, 0.f);
                    out[(size_t)row * ldo + col] = d;
                    out[(size_t)col * ldo + row] = d;
                }
            }
        }
    }
}

// ---------------- conversion kernels ----------------
// fused: o1 row -> hi/lo bf16 (padded) + row sum-of-squares
__global__ __launch_bounds__(256)
void splitsq_k(const float* __restrict__ o1, __nv_bfloat16* __restrict__ hi,
               __nv_bfloat16* __restrict__ lo, float* __restrict__ sq) {
    __shared__ float red[256];
    const int row = blockIdx.x, tid = threadIdx.x;
    float s = 0.f;
    for (int c = tid; c < CH; c += 256) {
        float v = o1[(size_t)row * CH + c];
        s = fmaf(v, v, s);
        __nv_bfloat16 h = __float2bfloat16_rn(v);
        __nv_bfloat16 l = __float2bfloat16_rn(v - __bfloat162float(h));
        size_t o = (size_t)row * KPAD + c;
        hi[o] = h;
        lo[o] = l;
    }
    red[tid] = s;
    __syncthreads();
    for (int st = 128; st > 0; st >>= 1) {
        if (tid < st) red[tid] += red[tid + st];
        __syncthreads();
    }
    if (tid == 0) sq[row] = red[0];
}

__global__ void w2t_k(const float* __restrict__ W2, __nv_bfloat16* __restrict__ w2t) {
    __shared__ float tile[32][33];
    int kk = blockIdx.z;
    int k0 = blockIdx.x * 32, n0 = blockIdx.y * 32;
    int tx = threadIdx.x, ty = threadIdx.y;
    int k = k0 + ty, n = n0 + tx;
    tile[ty][tx] = (k < CH && n < CH) ? W2[(size_t)(kk * CH + k) * CH + n] : 0.f;
    __syncthreads();
    int kw = k0 + tx, nw = n0 + ty;
    if (kw < CH && nw < CH)
        w2t[(size_t)kk * KPAD * KPAD + (size_t)nw * KPAD + kw] = __float2bfloat16_rn(tile[tx][ty]);
}

// ---------------- fp32 kernels ----------------
__global__ void rowsq_k(const float* __restrict__ X, float* __restrict__ sq, int F) {
    __shared__ float red[128];
    int row = blockIdx.x;
    float s = 0.f;
    for (int f = threadIdx.x; f < F; f += blockDim.x) {
        float v = X[(size_t)row * F + f];
        s += v * v;
    }
    red[threadIdx.x] = s;
    __syncthreads();
    for (int st = 64; st > 0; st >>= 1) {
        if (threadIdx.x < st) red[threadIdx.x] += red[threadIdx.x + st];
        __syncthreads();
    }
    if (threadIdx.x == 0) sq[row] = red[0];
}

// MODE: 0 store, 1 accumulate, 2 adj-dsq (full grid, coalesced store), 3 bias+relu
template <int TRANSB, int MODE>
__global__ void sgemm_k(const float* __restrict__ A, const float* __restrict__ B,
                        float* __restrict__ C, int M, int N, int K,
                        const float* __restrict__ sq) {
    __shared__ float As[8][128];
    __shared__ float Bs[8][128];
    const int tid = threadIdx.x;
    const int tx = tid & 15, ty = tid >> 4;
    const int m0 = blockIdx.y * 128, n0 = blockIdx.x * 128;
    float acc[8][8];
#pragma unroll
    for (int i = 0; i < 8; i++)
#pragma unroll
        for (int j = 0; j < 8; j++) acc[i][j] = 0.f;
    const int lrow = tid >> 1;
    const int lk = (tid & 1) * 4;
    const int bkr = tid >> 5;
    const int bnc = (tid & 31) * 4;
    for (int k0 = 0; k0 < K; k0 += 8) {
        {
            int m = m0 + lrow;
#pragma unroll
            for (int j = 0; j < 4; j++) {
                int k = k0 + lk + j;
                As[lk + j][lrow] = (m < M && k < K) ? A[(size_t)m * K + k] : 0.f;
            }
        }
        if (TRANSB) {
            int n = n0 + lrow;
#pragma unroll
            for (int j = 0; j < 4; j++) {
                int k = k0 + lk + j;
                Bs[lk + j][lrow] = (n < N && k < K) ? B[(size_t)n * K + k] : 0.f;
            }
        } else {
            int k = k0 + bkr;
#pragma unroll
            for (int j = 0; j < 4; j++) {
                int n = n0 + bnc + j;
                Bs[bkr][bnc + j] = (k < K && n < N) ? B[(size_t)k * N + n] : 0.f;
            }
        }
        __syncthreads();
#pragma unroll
        for (int kk = 0; kk < 8; kk++) {
            float ra[8], rb[8];
#pragma unroll
            for (int i = 0; i < 8; i++) ra[i] = As[kk][ty * 8 + i];
#pragma unroll
            for (int j = 0; j < 8; j++) rb[j] = Bs[kk][tx * 8 + j];
#pragma unroll
            for (int i = 0; i < 8; i++)
#pragma unroll
                for (int j = 0; j < 8; j++) acc[i][j] = fmaf(ra[i], rb[j], acc[i][j]);
        }
        __syncthreads();
    }
#pragma unroll
    for (int i = 0; i < 8; i++) {
        int m = m0 + ty * 8 + i;
        if (m >= M) continue;
#pragma unroll
        for (int j = 0; j < 8; j++) {
            int n = n0 + tx * 8 + j;
            if (n >= N) continue;
            size_t o = (size_t)m * N + n;
            if (MODE == 0) C[o] = acc[i][j];
            else if (MODE == 1) C[o] += acc[i][j];
            else if (MODE == 2) C[o] = fmaxf(sq[m] + sq[n] - 2.f * acc[i][j], 0.f);
            else C[o] = fmaxf(acc[i][j] + sq[n], 0.f);
        }
    }
}

// per-row 40-SMALLEST d^2 via 4-level radix select on float bits (non-negative floats:
// uint order == float order). Tie -> smallest index. kval = exp(-d^2) applied to
// winners only (exp is monotone decreasing: smallest d^2 == largest weights).
__global__ __launch_bounds__(256)
void topkr_k(const float* __restrict__ adj, int* __restrict__ kidx,
             float* __restrict__ kval, float* __restrict__ deg) {
    __shared__ uint32_t sv[NPTS];
    __shared__ uint32_t hist[256];
    __shared__ uint32_t s_stat[3];
    __shared__ uint32_t wcg[8], wce[8];
    __shared__ float red[256];
    const int row = blockIdx.x, tid = threadIdx.x;
    const int warp = tid >> 5, lane = tid & 31;
    const float* a = adj + (size_t)row * NPTS;
    for (int j = tid; j < NPTS; j += 256) sv[j] = __float_as_uint(a[j]);
    if (tid == 0) { s_stat[0] = 0; s_stat[1] = 0; s_stat[2] = KNN; }

#pragma unroll
    for (int lvl = 0; lvl < 4; lvl++) {
        hist[tid] = 0;
        __syncthreads();
        const int shift = 24 - lvl * 8;
        const uint32_t pmask = (lvl == 0) ? 0u : (0xFFFFFFFFu << (shift + 8));
        const uint32_t pref = s_stat[0];
        for (int j = tid; j < NPTS; j += 256) {
            uint32_t b = sv[j];
            if ((b & pmask) == pref) atomicAdd(&hist[(b >> shift) & 0xFF], 1u);
        }
        __syncthreads();
        if (tid == 0) {
            uint32_t need = s_stat[2], run = 0;
            int bsel = 255;
            for (int b = 0; b < 256; b++) {           // ascending: select smallest
                if (run + hist[b] >= need) { bsel = b; break; }
                run += hist[b];
            }
            s_stat[0] = pref | ((uint32_t)bsel << shift);
            s_stat[1] += run;
            s_stat[2] = need - run;
        }
        __syncthreads();
    }
    const uint32_t vstar = s_stat[0];
    const uint32_t cnt_lt = s_stat[1];
    const uint32_t rem = s_stat[2];
    const float evstar = __expf(-__uint_as_float(vstar));

    uint32_t run_lt = 0, run_eq = 0;
    float gsum = 0.f;
    for (int base = 0; base < NPTS; base += 256) {
        uint32_t b = sv[base + tid];
        bool lt = b < vstar, eq = (b == vstar);
        uint32_t mg = __ballot_sync(0xffffffffu, lt);
        uint32_t me = __ballot_sync(0xffffffffu, eq);
        if (lane == 0) { wcg[warp] = __popc(mg); wce[warp] = __popc(me); }
        __syncthreads();
        uint32_t pg = 0, tg = 0, pe = 0, te = 0;
#pragma unroll
        for (int w = 0; w < 8; w++) {
            if (w < warp) { pg += wcg[w]; pe += wce[w]; }
            tg += wcg[w]; te += wce[w];
        }
        const uint32_t lm = (1u << lane) - 1u;
        if (lt) {
            uint32_t p = run_lt + pg + __popc(mg & lm);
            float ev = __expf(-__uint_as_float(b));
            kidx[row * KNN + p] = base + tid;
            kval[row * KNN + p] = ev;
            gsum += ev;
        }
        if (eq) {
            uint32_t rk = run_eq + pe + __popc(me & lm);
            if (rk < rem) {
                uint32_t p = cnt_lt + rk;
                kidx[row * KNN + p] = base + tid;
                kval[row * KNN + p] = evstar;
            }
        }
        run_lt += tg;
        run_eq += te;
        __syncthreads();
    }
    red[tid] = gsum;
    __syncthreads();
    for (int s = 128; s > 0; s >>= 1) {
        if (tid < s) red[tid] += red[tid + s];
        __syncthreads();
    }
    if (tid == 0) deg[row] = red[0] + (float)rem * evstar;
}

__global__ void buildL_k(const int* __restrict__ kidx, const float* __restrict__ kval,
                         const float* __restrict__ deg, float* __restrict__ lval) {
    int e = blockIdx.x * blockDim.x + threadIdx.x;
    if (e >= NPTS * KNN) return;
    int i = e / KNN;
    int j = kidx[e];
    float di = 1.f / sqrtf(deg[i]);
    float dj = 1.f / sqrtf(deg[j]);
    lval[e] = -kval[e] * di * dj;
}

__global__ void spmm_k(const int* __restrict__ kidx, const float* __restrict__ lval,
                       const float* __restrict__ T, const float* __restrict__ P,
                       float* __restrict__ Y, int F, int mode) {
    __shared__ int sidx[KNN];
    __shared__ float sval[KNN];
    int row = blockIdx.x;
    if (threadIdx.x < KNN) {
        sidx[threadIdx.x] = kidx[row * KNN + threadIdx.x];
        sval[threadIdx.x] = lval[row * KNN + threadIdx.x];
    }
    __syncthreads();
    for (int f = threadIdx.x; f < F; f += blockDim.x) {
        float acc = T[(size_t)row * F + f];
#pragma unroll 8
        for (int t = 0; t < KNN; t++) acc = fmaf(sval[t], T[(size_t)sidx[t] * F + f], acc);
        if (mode == 1) acc = 2.f * acc - P[(size_t)row * F + f];
        Y[(size_t)row * F + f] = acc;
    }
}

__global__ void spmm4b_k(const int* __restrict__ kidx, const float* __restrict__ lval,
                         const float4* __restrict__ T, const float4* __restrict__ P,
                         float4* __restrict__ Y, __nv_bfloat16* __restrict__ Ybf, int mode) {
    __shared__ int sidx[KNN];
    __shared__ float sval[KNN];
    const int F4 = CH / 4;
    int row = blockIdx.x;
    if (threadIdx.x < KNN) {
        sidx[threadIdx.x] = kidx[row * KNN + threadIdx.x];
        sval[threadIdx.x] = lval[row * KNN + threadIdx.x];
    }
    __syncthreads();
    for (int f = threadIdx.x; f < F4; f += blockDim.x) {
        float4 a = T[(size_t)row * F4 + f];
#pragma unroll 8
        for (int t = 0; t < KNN; t++) {
            float4 v = T[(size_t)sidx[t] * F4 + f];
            float s = sval[t];
            a.x = fmaf(s, v.x, a.x);
            a.y = fmaf(s, v.y, a.y);
            a.z = fmaf(s, v.z, a.z);
            a.w = fmaf(s, v.w, a.w);
        }
        if (mode == 1) {
            float4 p = P[(size_t)row * F4 + f];
            a.x = 2.f * a.x - p.x;
            a.y = 2.f * a.y - p.y;
            a.z = 2.f * a.z - p.z;
            a.w = 2.f * a.w - p.w;
        }
        Y[(size_t)row * F4 + f] = a;
        __nv_bfloat162* d2 = (__nv_bfloat162*)(Ybf + (size_t)row * KPAD + 4 * f);
        d2[0] = __floats2bfloat162_rn(a.x, a.y);
        d2[1] = __floats2bfloat162_rn(a.z, a.w);
    }
}

__global__ void pack3_k(const float* __restrict__ A, const float* __restrict__ B,
                        const float* __restrict__ C, float* __restrict__ Y, int M, int F) {
    int i = blockIdx.x * blockDim.x + threadIdx.x;
    if (i >= M * F) return;
    int r = i / F, f = i % F;
    size_t o = (size_t)r * 3 * F + f;
    Y[o] = A[i];
    Y[o + F] = B[i];
    Y[o + 2 * F] = C[i];
}

// split-K regmat stage 1
__global__ void regmat1_k(const float* __restrict__ O, const float* __restrict__ Tf,
                          float* __restrict__ part) {
    __shared__ float sT[128][FIN];
    int c = blockIdx.x * 128 + threadIdx.x;
    int n0 = blockIdx.y * 128;
    for (int i = threadIdx.x; i < 128 * FIN; i += 128) sT[i / FIN][i % FIN] = Tf[(n0 + i / FIN) * FIN + i % FIN];
    __syncthreads();
    float a[FIN] = {0, 0, 0, 0, 0, 0};
    if (c < CH) {
        for (int n = 0; n < 128; n++) {
            float o = O[(size_t)(n0 + n) * CH + c];
#pragma unroll
            for (int f = 0; f < FIN; f++) a[f] = fmaf(o, sT[n][f], a[f]);
        }
#pragma unroll
        for (int f = 0; f < FIN; f++) part[((size_t)blockIdx.y * CH + c) * FIN + f] = a[f];
    }
}

__global__ void regmat2_k(const float* __restrict__ part, float* __restrict__ Mo) {
    int i = blockIdx.x * 256 + threadIdx.x;
    if (i >= CH * FIN) return;
    float s = 0.f;
    for (int k = 0; k < 32; k++) s += part[(size_t)k * CH * FIN + i];
    Mo[i] = s;
}

__global__ void fro_k(const float* __restrict__ v, int n, float* __restrict__ dst) {
    __shared__ float red[256];
    float s = 0.f;
    for (int i = threadIdx.x; i < n; i += 256) { float x = v[i]; s += x * x; }
    red[threadIdx.x] = s;
    __syncthreads();
    for (int st = 128; st > 0; st >>= 1) {
        if (threadIdx.x < st) red[threadIdx.x] += red[threadIdx.x + st];
        __syncthreads();
    }
    if (threadIdx.x == 0) dst[0] = sqrtf(red[0]);
}

__global__ void reebpool_k(const float* __restrict__ O, const int* __restrict__ sccs,
                           float* __restrict__ vfr) {
    __shared__ int sidx[SCC];
    int r = blockIdx.x;
    for (int i = threadIdx.x; i < SCC; i += blockDim.x) sidx[i] = sccs[r * SCC + i];
    __syncthreads();
    int c = blockIdx.y * 256 + threadIdx.x;
    if (c >= CH) return;
    float m = -FLT_MAX;
    for (int s = 0; s < SCC; s++) m = fmaxf(m, O[(size_t)sidx[s] * CH + c]);
    vfr[r * CH + c] = m;
}

// fused Reeb Chebyshev prep: per column c compute T1 = Lr@vfr, T2 = 2Lr@T1 - vfr,
// write packed xhr = [vfr | T1 | T2].
__global__ void reebfuse_k(const float* __restrict__ Lr, const float* __restrict__ vfr,
                           float* __restrict__ xhr) {
    __shared__ float sL[NRB * NRB];
    for (int i = threadIdx.x; i < NRB * NRB; i += blockDim.x) sL[i] = Lr[i];
    __syncthreads();
    int c = blockIdx.x * blockDim.x + threadIdx.x;
    if (c >= CH) return;
    float v0[NRB], t1[NRB];
#pragma unroll
    for (int q = 0; q < NRB; q++) v0[q] = vfr[q * CH + c];
#pragma unroll
    for (int r = 0; r < NRB; r++) {
        float a = 0.f;
#pragma unroll
        for (int q = 0; q < NRB; q++) a = fmaf(sL[r * NRB + q], v0[q], a);
        t1[r] = a;
    }
#pragma unroll
    for (int r = 0; r < NRB; r++) {
        float a = 0.f;
#pragma unroll
        for (int q = 0; q < NRB; q++) a = fmaf(sL[r * NRB + q], t1[q], a);
        float t2 = 2.f * a - v0[r];
        xhr[(size_t)r * 3 * CH + c] = v0[r];
        xhr[(size_t)r * 3 * CH + CH + c] = t1[r];
        xhr[(size_t)r * 3 * CH + 2 * CH + c] = t2;
    }
}

__global__ void colmax1_k(const float* __restrict__ X, float* __restrict__ part) {
    int c = blockIdx.x * 256 + threadIdx.x;
    if (c >= CH) return;
    int r0 = blockIdx.y * 128;
    float m = -FLT_MAX;
    for (int r = r0; r < r0 + 128; r++) m = fmaxf(m, X[(size_t)r * CH + c]);
    part[(size_t)blockIdx.y * CH + c] = m;
}

__global__ void colmax2_k(const float* __restrict__ part, float* __restrict__ y) {
    int c = blockIdx.x * 256 + threadIdx.x;
    if (c >= CH) return;
    float m = -FLT_MAX;
    for (int k = 0; k < 32; k++) m = fmaxf(m, part[(size_t)k * CH + c]);
    y[c] = m;
}

__global__ void colmax_k(const float* __restrict__ X, int M, int N, float* __restrict__ y) {
    int c = blockIdx.x * blockDim.x + threadIdx.x;
    if (c >= N) return;
    float m = -FLT_MAX;
    for (int r = 0; r < M; r++) m = fmaxf(m, X[(size_t)r * N + c]);
    y[c] = m;
}

__global__ void fc1a_k(const float* __restrict__ v, const float* __restrict__ W,
                       float* __restrict__ part) {
    int j = blockIdx.x * 128 + threadIdx.x;
    int i0 = blockIdx.y * 125;
    float acc = 0.f;
    for (int i = i0; i < i0 + 125; i++) acc = fmaf(v[i], W[(size_t)i * 512 + j], acc);
    part[(size_t)blockIdx.y * 512 + j] = acc;
}

__global__ void fc1b_k(const float* __restrict__ part, const float* __restrict__ b,
                       float* __restrict__ y) {
    int j = blockIdx.x * 128 + threadIdx.x;
    float acc = b[j];
    for (int k = 0; k < 16; k++) acc += part[(size_t)k * 512 + j];
    y[j] = fmaxf(acc, 0.f);
}

__global__ void fc_k(const float* __restrict__ v, const float* __restrict__ W,
                     const float* __restrict__ b, float* __restrict__ y,
                     int In, int Out, int relu) {
    int j = blockIdx.x * blockDim.x + threadIdx.x;
    if (j >= Out) return;
    float acc = b[j];
    for (int i = 0; i < In; i++) acc = fmaf(v[i], W[(size_t)i * Out + j], acc);
    if (relu) acc = fmaxf(acc, 0.f);
    y[j] = acc;
}

__global__ void wregs_k(const float* __restrict__ w1, const float* __restrict__ b1,
                        const float* __restrict__ w2, const float* __restrict__ b2,
                        const float* __restrict__ w3, const float* __restrict__ b3,
                        float* __restrict__ dst) {
    __shared__ float red[256];
    float s = 0.f;
    for (int i = threadIdx.x; i < 2000; i += 256) { float v = w1[(size_t)i * 512]; s += v * v; }
    red[threadIdx.x] = s;
    __syncthreads();
    for (int st = 128; st > 0; st >>= 1) {
        if (threadIdx.x < st) red[threadIdx.x] += red[threadIdx.x + st];
        __syncthreads();
    }
    if (threadIdx.x == 0) dst[2] = red[0];
    __syncthreads();
    s = 0.f;
    for (int i = threadIdx.x; i < 512; i += 256) { float v = w2[(size_t)i * 128]; s += v * v; }
    red[threadIdx.x] = s;
    __syncthreads();
    for (int st = 128; st > 0; st >>= 1) {
        if (threadIdx.x < st) red[threadIdx.x] += red[threadIdx.x + st];
        __syncthreads();
    }
    if (threadIdx.x == 0) dst[4] = red[0];
    __syncthreads();
    s = 0.f;
    for (int i = threadIdx.x; i < 128; i += 256) { float v = w3[(size_t)i * 40]; s += v * v; }
    red[threadIdx.x] = s;
    __syncthreads();
    for (int st = 128; st > 0; st >>= 1) {
        if (threadIdx.x < st) red[threadIdx.x] += red[threadIdx.x + st];
        __syncthreads();
    }
    if (threadIdx.x == 0) {
        dst[6] = red[0];
        dst[3] = b1[0] * b1[0];
        dst[5] = b2[0] * b2[0];
        dst[7] = b3[0] * b3[0];
    }
}

// ---------------- host launch ----------------
extern "C" void kernel_launch(void* const* d_in, const int* in_sizes, int n_in,
                              void* d_out, int out_size) {
    const float* x    = (const float*)d_in[0];
    const float* Lr   = (const float*)d_in[5];
    const int*   sccs = (const int*)d_in[6];
    const float* W1   = (const float*)d_in[7];
    const float* b1   = (const float*)d_in[8];
    const float* W2   = (const float*)d_in[9];
    const float* b2   = (const float*)d_in[10];
    const float* Wr   = (const float*)d_in[11];
    const float* br   = (const float*)d_in[12];
    const float* f1w  = (const float*)d_in[13];
    const float* f1b  = (const float*)d_in[14];
    const float* f2w  = (const float*)d_in[15];
    const float* f2b  = (const float*)d_in[16];
    const float* f3w  = (const float*)d_in[17];
    const float* f3b  = (const float*)d_in[18];
    float* out = (float*)d_out;

    float *adj, *sq, *kval, *deg, *lval, *o1, *ta, *tb, *accb, *t1a, *t2a, *xh1;
    float *l2x, *Mb, *vfr, *xhr, *reeb, *of, *fc1o, *fc2o, *part;
    int* kidx;
    __nv_bfloat16 *tbf, *o1l, *w2t;
    cudaGetSymbolAddress((void**)&adj, g_adj);
    cudaGetSymbolAddress((void**)&sq, g_sq);
    cudaGetSymbolAddress((void**)&kidx, g_kidx);
    cudaGetSymbolAddress((void**)&kval, g_kval);
    cudaGetSymbolAddress((void**)&deg, g_deg);
    cudaGetSymbolAddress((void**)&lval, g_lval);
    cudaGetSymbolAddress((void**)&o1, g_o1);
    cudaGetSymbolAddress((void**)&ta, g_ta);
    cudaGetSymbolAddress((void**)&tb, g_tb);
    cudaGetSymbolAddress((void**)&accb, g_accb);
    cudaGetSymbolAddress((void**)&t1a, g_t1a);
    cudaGetSymbolAddress((void**)&t2a, g_t2a);
    cudaGetSymbolAddress((void**)&xh1, g_xh1);
    cudaGetSymbolAddress((void**)&l2x, g_l2x);
    cudaGetSymbolAddress((void**)&Mb, g_Mb);
    cudaGetSymbolAddress((void**)&vfr, g_vfr);
    cudaGetSymbolAddress((void**)&xhr, g_xhr);
    cudaGetSymbolAddress((void**)&reeb, g_reeb);
    cudaGetSymbolAddress((void**)&of, g_of);
    cudaGetSymbolAddress((void**)&fc1o, g_fc1);
    cudaGetSymbolAddress((void**)&fc2o, g_fc2);
    cudaGetSymbolAddress((void**)&part, g_part);
    cudaGetSymbolAddress((void**)&tbf, g_tbf);
    cudaGetSymbolAddress((void**)&o1l, g_o1l);
    cudaGetSymbolAddress((void**)&w2t, g_w2t);

    const int BF_SMEM = 2 * 2 * 128 * 72 * 2;   // 73728 B
    cudaFuncSetAttribute(bfmma_k<0>, cudaFuncAttributeMaxDynamicSharedMemorySize, BF_SMEM);
    cudaFuncSetAttribute(bfmma_k<1>, cudaFuncAttributeMaxDynamicSharedMemorySize, BF_SMEM);

    dim3 gBig(32, 32);
    dim3 gC1(8, 32);
    dim3 gRb(8, 1);
    const size_t SLOT = (size_t)NPTS * KPAD;

    // ---- graph 1 (exact fp32; d^2 full grid coalesced, exp deferred to topk) ----
    rowsq_k<<<NPTS, 128>>>(x, sq, FIN);
    sgemm_k<1, 2><<<gBig, 256>>>(x, x, adj, NPTS, NPTS, FIN, sq);
    topkr_k<<<NPTS, 256>>>(adj, kidx, kval, deg);
    buildL_k<<<(NPTS * KNN + 255) / 256, 256>>>(kidx, kval, deg, lval);

    // ---- cheb conv 1 (exact fp32, fused bias+relu) ----
    spmm_k<<<NPTS, 64>>>(kidx, lval, x, (const float*)0, t1a, FIN, 0);
    spmm_k<<<NPTS, 64>>>(kidx, lval, t1a, x, t2a, FIN, 1);
    pack3_k<<<(NPTS * FIN + 255) / 256, 256>>>(x, t1a, t2a, xh1, NPTS, FIN);
    sgemm_k<0, 3><<<gC1, 256>>>(xh1, W1, o1, NPTS, CH, 3 * FIN, b1);

    // ---- reg1 (split-K) ----
    regmat1_k<<<dim3(8, 32), 128>>>(o1, t1a, part);
    regmat2_k<<<(CH * FIN + 255) / 256, 256>>>(part, Mb);
    if (out_size >= 48) fro_k<<<1, 256>>>(Mb, CH * FIN, out + 40);

    reebpool_k<<<dim3(NRB, 4), 256>>>(o1, sccs, vfr);

    // ---- graph 2 (bf16 mma, split hi/lo; d^2 epilogue, exp deferred) ----
    splitsq_k<<<NPTS, 256>>>(o1, tbf, o1l, sq);
    w2t_k<<<dim3(32, 32, 6), dim3(32, 32)>>>(W2, w2t);
    {
        BfSegs s;
        s.a[0] = tbf;  s.b[0] = tbf;   // hi.hi^T
        s.a[1] = tbf;  s.b[1] = o1l;   // hi.lo^T
        s.a[2] = o1l;  s.b[2] = tbf;   // lo.hi^T
        s.a[3] = s.a[4] = s.a[5] = tbf;
        s.b[3] = s.b[4] = s.b[5] = tbf;
        bfmma_k<1><<<gBig, 256, BF_SMEM>>>(s, 3, KPAD, KPAD, sq, adj, NPTS, NPTS);
    }
    topkr_k<<<NPTS, 256>>>(adj, kidx, kval, deg);
    buildL_k<<<(NPTS * KNN + 255) / 256, 256>>>(kidx, kval, deg, lval);

    // ---- Chebyshev recursion (fp32) + bf16 snapshots ----
    spmm4b_k<<<NPTS, 256>>>(kidx, lval, (const float4*)o1, (const float4*)0,
                            (float4*)ta, tbf + 1 * SLOT, 0);
    spmm4b_k<<<NPTS, 256>>>(kidx, lval, (const float4*)ta, (const float4*)o1,
                            (float4*)tb, tbf + 2 * SLOT, 1);
    spmm4b_k<<<NPTS, 256>>>(kidx, lval, (const float4*)tb, (const float4*)ta,
                            (float4*)o1, tbf + 3 * SLOT, 1);
    spmm4b_k<<<NPTS, 256>>>(kidx, lval, (const float4*)o1, (const float4*)tb,
                            (float4*)ta, tbf + 4 * SLOT, 1);
    spmm4b_k<<<NPTS, 256>>>(kidx, lval, (const float4*)ta, (const float4*)o1,
                            (float4*)tb, tbf + 5 * SLOT, 1);

    // ---- fused cheb conv 2 ----
    {
        BfSegs s;
        for (int i = 0; i < 6; i++) {
            s.a[i] = tbf + (size_t)i * SLOT;
            s.b[i] = w2t + (size_t)i * KPAD * KPAD;
        }
        bfmma_k<0><<<gC1, 256, BF_SMEM>>>(s, 6, KPAD, KPAD, b2, accb, CH, CH);
    }

    // ---- reg2 (split-K) ----
    spmm_k<<<NPTS, 64>>>(kidx, lval, x, (const float*)0, l2x, FIN, 0);
    regmat1_k<<<dim3(8, 32), 128>>>(accb, l2x, part);
    regmat2_k<<<(CH * FIN + 255) / 256, 256>>>(part, Mb);
    if (out_size >= 48) fro_k<<<1, 256>>>(Mb, CH * FIN, out + 41);

    // ---- Reeb branch (exact fp32, fused) ----
    reebfuse_k<<<(CH + 255) / 256, 256>>>(Lr, vfr, xhr);
    sgemm_k<0, 3><<<gRb, 256>>>(xhr, Wr, reeb, NRB, CH, 3 * CH, br);

    // ---- head ----
    colmax_k<<<(CH + 255) / 256, 256>>>(reeb, NRB, CH, of);
    colmax1_k<<<dim3(4, 32), 256>>>(accb, part);
    colmax2_k<<<4, 256>>>(part, of + CH);
    fc1a_k<<<dim3(4, 16), 128>>>(of, f1w, part);
    fc1b_k<<<4, 128>>>(part, f1b, fc1o);
    fc_k<<<1, 128>>>(fc1o, f2w, f2b, fc2o, 512, 128, 1);
    fc_k<<<1, 64>>>(fc2o, f3w, f3b, out, 128, 40, 0);

    if (out_size >= 48) wregs_k<<<1, 256>>>(f1w, f1b, f2w, f2b, f3w, f3b, out + 40);
}

// round 14
// speedup vs baseline: 1.0464x; 1.0464x over previous
#include <cuda_runtime.h>
#include <cuda_bf16.h>
#include <math.h>
#include <float.h>
#include <stdint.h>

#define NPTS 4096
#define FIN  6
#define CH   1000
#define KPAD 1024
#define KNN  40
#define NRB  20
#define SCC  205

// ---------------- scratch (device globals; zero-init at module load) ----------------
__device__ float g_adj[(size_t)NPTS * NPTS];      // holds d^2
__device__ float g_sq[NPTS];
__device__ int   g_kidx[NPTS * KNN];
__device__ float g_kval[NPTS * KNN];
__device__ float g_deg[NPTS];
__device__ float g_lval[NPTS * KNN];
__device__ float g_o1[(size_t)NPTS * CH];
__device__ float g_ta[(size_t)NPTS * CH];
__device__ float g_tb[(size_t)NPTS * CH];
__device__ float g_accb[(size_t)NPTS * CH];
__device__ float g_t1a[NPTS * FIN];
__device__ float g_t2a[NPTS * FIN];
__device__ float g_xh1[NPTS * 3 * FIN];
__device__ float g_l2x[NPTS * FIN];
__device__ float g_Mb[CH * FIN];
__device__ float g_vfr[NRB * CH];
__device__ float g_xhr[NRB * 3 * CH];
__device__ float g_reeb[NRB * CH];
__device__ float g_of[2 * CH];
__device__ float g_fc1[512];
__device__ float g_fc2[128];
__device__ float g_part[32 * CH * FIN];           // split-K partials scratch
// bf16 operands (pads beyond col 999 / row 999 never written -> stay zero)
__device__ __nv_bfloat16 g_tbf[(size_t)6 * NPTS * KPAD];   // T0..T5 hi
__device__ __nv_bfloat16 g_o1l[(size_t)NPTS * KPAD];       // o1 lo residual
__device__ __nv_bfloat16 g_w2t[(size_t)6 * KPAD * KPAD];   // W2_k^T [n][k]

// ---------------- bf16 tensor-core GEMM (mma.sync.m16n8k16) ----------------
__device__ __forceinline__ void mma_bf16(float* c, const uint32_t* a, const uint32_t* b) {
    asm volatile(
        "mma.sync.aligned.m16n8k16.row.col.f32.bf16.bf16.f32 "
        "{%0,%1,%2,%3}, {%4,%5,%6,%7}, {%8,%9}, {%0,%1,%2,%3};\n"
        : "+f"(c[0]), "+f"(c[1]), "+f"(c[2]), "+f"(c[3])
        : "r"(a[0]), "r"(a[1]), "r"(a[2]), "r"(a[3]), "r"(b[0]), "r"(b[1]));
}

struct BfSegs {
    const __nv_bfloat16* a[6];
    const __nv_bfloat16* b[6];
};

// KIND 0: cheb  (out = relu(acc + aux[col]))
// KIND 1: adj   (out = max(aux[row]+aux[col]-2*acc, 0) = d^2; lower-tri blocks, mirrored)
// Block 128x128xK, 256 threads, 8 warps (2x4 of 64x32), BK=64, double-buffered smem.
template <int KIND>
__global__ __launch_bounds__(256)
void bfmma_k(BfSegs segs, int nseg, int lda, int ldb,
             const float* __restrict__ aux, float* __restrict__ out, int ldo, int ncap) {
    extern __shared__ __nv_bfloat16 dynsm[];          // [2][128][72] A then [2][128][72] B
    __nv_bfloat16* As = dynsm;
    __nv_bfloat16* Bs = dynsm + 2 * 128 * 72;
    const int tid = threadIdx.x, lane = tid & 31, warp = tid >> 5;
    const int wm0 = (warp & 1) * 64, wn0 = (warp >> 1) * 32;
    const int m0 = blockIdx.y * 128, n0 = blockIdx.x * 128;
    if (KIND == 1 && blockIdx.x > blockIdx.y) return;

    float acc[4][4][4];
#pragma unroll
    for (int i = 0; i < 4; i++)
#pragma unroll
        for (int j = 0; j < 4; j++)
#pragma unroll
            for (int q = 0; q < 4; q++) acc[i][j][q] = 0.f;

    const int lrow = tid >> 1, lko = (tid & 1) * 32;
    uint4 Ar[4], Br[4];
    const int ntiles = nseg * 16;

    {   // prologue: tile 0 -> buf 0
        const uint4* pa = (const uint4*)(segs.a[0] + (size_t)(m0 + lrow) * lda + lko);
        const uint4* pb = (const uint4*)(segs.b[0] + (size_t)(n0 + lrow) * ldb + lko);
#pragma unroll
        for (int j = 0; j < 4; j++) { Ar[j] = pa[j]; Br[j] = pb[j]; }
        uint4* da = (uint4*)&As[(size_t)lrow * 72 + lko];
        uint4* db = (uint4*)&Bs[(size_t)lrow * 72 + lko];
#pragma unroll
        for (int j = 0; j < 4; j++) { da[j] = Ar[j]; db[j] = Br[j]; }
    }
    __syncthreads();

    for (int t = 0; t < ntiles; t++) {
        const int bufe = (t & 1) ? (128 * 72) : 0;    // element offset of current buffer
        if (t + 1 < ntiles) {
            int s = t + 1;
            int seg = s >> 4, kw = (s & 15) * 64;
            const uint4* pa = (const uint4*)(segs.a[seg] + (size_t)(m0 + lrow) * lda + kw + lko);
            const uint4* pb = (const uint4*)(segs.b[seg] + (size_t)(n0 + lrow) * ldb + kw + lko);
#pragma unroll
            for (int j = 0; j < 4; j++) { Ar[j] = pa[j]; Br[j] = pb[j]; }
        }
        const __nv_bfloat16* Ab = As + bufe;
        const __nv_bfloat16* Bb = Bs + bufe;
        const int gr = lane >> 2, gc = lane & 3;
#pragma unroll
        for (int kk = 0; kk < 64; kk += 16) {
            uint32_t au[4][4], bu[4][2];
#pragma unroll
            for (int mi = 0; mi < 4; mi++) {
                int r = wm0 + mi * 16 + gr;
                au[mi][0] = *(const uint32_t*)&Ab[r * 72 + kk + gc * 2];
                au[mi][1] = *(const uint32_t*)&Ab[(r + 8) * 72 + kk + gc * 2];
                au[mi][2] = *(const uint32_t*)&Ab[r * 72 + kk + 8 + gc * 2];
                au[mi][3] = *(const uint32_t*)&Ab[(r + 8) * 72 + kk + 8 + gc * 2];
            }
#pragma unroll
            for (int ni = 0; ni < 4; ni++) {
                int n = wn0 + ni * 8 + gr;
                bu[ni][0] = *(const uint32_t*)&Bb[n * 72 + kk + gc * 2];
                bu[ni][1] = *(const uint32_t*)&Bb[n * 72 + kk + 8 + gc * 2];
            }
#pragma unroll
            for (int mi = 0; mi < 4; mi++)
#pragma unroll
                for (int ni = 0; ni < 4; ni++) mma_bf16(acc[mi][ni], au[mi], bu[ni]);
        }
        if (t + 1 < ntiles) {
            const int nbuf = ((t + 1) & 1) ? (128 * 72) : 0;
            uint4* da = (uint4*)&As[nbuf + (size_t)lrow * 72 + lko];
            uint4* db = (uint4*)&Bs[nbuf + (size_t)lrow * 72 + lko];
#pragma unroll
            for (int j = 0; j < 4; j++) { da[j] = Ar[j]; db[j] = Br[j]; }
            __syncthreads();
        }
    }

    const int gr = lane >> 2, gc2 = (lane & 3) * 2;
#pragma unroll
    for (int mi = 0; mi < 4; mi++) {
#pragma unroll
        for (int ni = 0; ni < 4; ni++) {
#pragma unroll
            for (int q = 0; q < 4; q++) {
                int row = m0 + wm0 + mi * 16 + gr + ((q >= 2) ? 8 : 0);
                int col = n0 + wn0 + ni * 8 + gc2 + (q & 1);
                float v = acc[mi][ni][q];
                if (KIND == 0) {
                    if (col < ncap)
                        out[(size_t)row * ldo + col] = fmaxf(v + aux[col], 0.f);
                } else {
                    float d = fmaxf(aux[row] + aux[col] - 2.f * v, 0.f);
                    out[(size_t)row * ldo + col] = d;
                    out[(size_t)col * ldo + row] = d;
                }
            }
        }
    }
}

// ---------------- conversion kernels ----------------
// fused: o1 row -> hi/lo bf16 (padded) + row sum-of-squares
__global__ __launch_bounds__(256)
void splitsq_k(const float* __restrict__ o1, __nv_bfloat16* __restrict__ hi,
               __nv_bfloat16* __restrict__ lo, float* __restrict__ sq) {
    __shared__ float red[256];
    const int row = blockIdx.x, tid = threadIdx.x;
    float s = 0.f;
    for (int c = tid; c < CH; c += 256) {
        float v = o1[(size_t)row * CH + c];
        s = fmaf(v, v, s);
        __nv_bfloat16 h = __float2bfloat16_rn(v);
        __nv_bfloat16 l = __float2bfloat16_rn(v - __bfloat162float(h));
        size_t o = (size_t)row * KPAD + c;
        hi[o] = h;
        lo[o] = l;
    }
    red[tid] = s;
    __syncthreads();
    for (int st = 128; st > 0; st >>= 1) {
        if (tid < st) red[tid] += red[tid + st];
        __syncthreads();
    }
    if (tid == 0) sq[row] = red[0];
}

__global__ void w2t_k(const float* __restrict__ W2, __nv_bfloat16* __restrict__ w2t) {
    __shared__ float tile[32][33];
    int kk = blockIdx.z;
    int k0 = blockIdx.x * 32, n0 = blockIdx.y * 32;
    int tx = threadIdx.x, ty = threadIdx.y;
    int k = k0 + ty, n = n0 + tx;
    tile[ty][tx] = (k < CH && n < CH) ? W2[(size_t)(kk * CH + k) * CH + n] : 0.f;
    __syncthreads();
    int kw = k0 + tx, nw = n0 + ty;
    if (kw < CH && nw < CH)
        w2t[(size_t)kk * KPAD * KPAD + (size_t)nw * KPAD + kw] = __float2bfloat16_rn(tile[tx][ty]);
}

// ---------------- fp32 kernels ----------------
__global__ void rowsq_k(const float* __restrict__ X, float* __restrict__ sq, int F) {
    __shared__ float red[128];
    int row = blockIdx.x;
    float s = 0.f;
    for (int f = threadIdx.x; f < F; f += blockDim.x) {
        float v = X[(size_t)row * F + f];
        s += v * v;
    }
    red[threadIdx.x] = s;
    __syncthreads();
    for (int st = 64; st > 0; st >>= 1) {
        if (threadIdx.x < st) red[threadIdx.x] += red[threadIdx.x + st];
        __syncthreads();
    }
    if (threadIdx.x == 0) sq[row] = red[0];
}

// MODE: 0 store, 1 accumulate, 2 adj-dsq (full grid, coalesced store), 3 bias+relu
template <int TRANSB, int MODE>
__global__ void sgemm_k(const float* __restrict__ A, const float* __restrict__ B,
                        float* __restrict__ C, int M, int N, int K,
                        const float* __restrict__ sq) {
    __shared__ float As[8][128];
    __shared__ float Bs[8][128];
    const int tid = threadIdx.x;
    const int tx = tid & 15, ty = tid >> 4;
    const int m0 = blockIdx.y * 128, n0 = blockIdx.x * 128;
    float acc[8][8];
#pragma unroll
    for (int i = 0; i < 8; i++)
#pragma unroll
        for (int j = 0; j < 8; j++) acc[i][j] = 0.f;
    const int lrow = tid >> 1;
    const int lk = (tid & 1) * 4;
    const int bkr = tid >> 5;
    const int bnc = (tid & 31) * 4;
    for (int k0 = 0; k0 < K; k0 += 8) {
        {
            int m = m0 + lrow;
#pragma unroll
            for (int j = 0; j < 4; j++) {
                int k = k0 + lk + j;
                As[lk + j][lrow] = (m < M && k < K) ? A[(size_t)m * K + k] : 0.f;
            }
        }
        if (TRANSB) {
            int n = n0 + lrow;
#pragma unroll
            for (int j = 0; j < 4; j++) {
                int k = k0 + lk + j;
                Bs[lk + j][lrow] = (n < N && k < K) ? B[(size_t)n * K + k] : 0.f;
            }
        } else {
            int k = k0 + bkr;
#pragma unroll
            for (int j = 0; j < 4; j++) {
                int n = n0 + bnc + j;
                Bs[bkr][bnc + j] = (k < K && n < N) ? B[(size_t)k * N + n] : 0.f;
            }
        }
        __syncthreads();
#pragma unroll
        for (int kk = 0; kk < 8; kk++) {
            float ra[8], rb[8];
#pragma unroll
            for (int i = 0; i < 8; i++) ra[i] = As[kk][ty * 8 + i];
#pragma unroll
            for (int j = 0; j < 8; j++) rb[j] = Bs[kk][tx * 8 + j];
#pragma unroll
            for (int i = 0; i < 8; i++)
#pragma unroll
                for (int j = 0; j < 8; j++) acc[i][j] = fmaf(ra[i], rb[j], acc[i][j]);
        }
        __syncthreads();
    }
#pragma unroll
    for (int i = 0; i < 8; i++) {
        int m = m0 + ty * 8 + i;
        if (m >= M) continue;
#pragma unroll
        for (int j = 0; j < 8; j++) {
            int n = n0 + tx * 8 + j;
            if (n >= N) continue;
            size_t o = (size_t)m * N + n;
            if (MODE == 0) C[o] = acc[i][j];
            else if (MODE == 1) C[o] += acc[i][j];
            else if (MODE == 2) C[o] = fmaxf(sq[m] + sq[n] - 2.f * acc[i][j], 0.f);
            else C[o] = fmaxf(acc[i][j] + sq[n], 0.f);
        }
    }
}

// per-row 40-SMALLEST d^2 via 4-level radix select on float bits (non-negative floats:
// uint order == float order). Tie -> smallest index. kval = exp(-d^2) applied to
// winners only (exp is monotone decreasing: smallest d^2 == largest weights).
__global__ __launch_bounds__(256)
void topkr_k(const float* __restrict__ adj, int* __restrict__ kidx,
             float* __restrict__ kval, float* __restrict__ deg) {
    __shared__ uint32_t sv[NPTS];
    __shared__ uint32_t hist[256];
    __shared__ uint32_t s_stat[3];
    __shared__ uint32_t wcg[8], wce[8];
    __shared__ float red[256];
    const int row = blockIdx.x, tid = threadIdx.x;
    const int warp = tid >> 5, lane = tid & 31;
    const float* a = adj + (size_t)row * NPTS;
    for (int j = tid; j < NPTS; j += 256) sv[j] = __float_as_uint(a[j]);
    if (tid == 0) { s_stat[0] = 0; s_stat[1] = 0; s_stat[2] = KNN; }

#pragma unroll
    for (int lvl = 0; lvl < 4; lvl++) {
        hist[tid] = 0;
        __syncthreads();
        const int shift = 24 - lvl * 8;
        const uint32_t pmask = (lvl == 0) ? 0u : (0xFFFFFFFFu << (shift + 8));
        const uint32_t pref = s_stat[0];
        for (int j = tid; j < NPTS; j += 256) {
            uint32_t b = sv[j];
            if ((b & pmask) == pref) atomicAdd(&hist[(b >> shift) & 0xFF], 1u);
        }
        __syncthreads();
        if (tid == 0) {
            uint32_t need = s_stat[2], run = 0;
            int bsel = 255;
            for (int b = 0; b < 256; b++) {           // ascending: select smallest
                if (run + hist[b] >= need) { bsel = b; break; }
                run += hist[b];
            }
            s_stat[0] = pref | ((uint32_t)bsel << shift);
            s_stat[1] += run;
            s_stat[2] = need - run;
        }
        __syncthreads();
    }
    const uint32_t vstar = s_stat[0];
    const uint32_t cnt_lt = s_stat[1];
    const uint32_t rem = s_stat[2];
    const float evstar = __expf(-__uint_as_float(vstar));

    uint32_t run_lt = 0, run_eq = 0;
    float gsum = 0.f;
    for (int base = 0; base < NPTS; base += 256) {
        uint32_t b = sv[base + tid];
        bool lt = b < vstar, eq = (b == vstar);
        uint32_t mg = __ballot_sync(0xffffffffu, lt);
        uint32_t me = __ballot_sync(0xffffffffu, eq);
        if (lane == 0) { wcg[warp] = __popc(mg); wce[warp] = __popc(me); }
        __syncthreads();
        uint32_t pg = 0, tg = 0, pe = 0, te = 0;
#pragma unroll
        for (int w = 0; w < 8; w++) {
            if (w < warp) { pg += wcg[w]; pe += wce[w]; }
            tg += wcg[w]; te += wce[w];
        }
        const uint32_t lm = (1u << lane) - 1u;
        if (lt) {
            uint32_t p = run_lt + pg + __popc(mg & lm);
            float ev = __expf(-__uint_as_float(b));
            kidx[row * KNN + p] = base + tid;
            kval[row * KNN + p] = ev;
            gsum += ev;
        }
        if (eq) {
            uint32_t rk = run_eq + pe + __popc(me & lm);
            if (rk < rem) {
                uint32_t p = cnt_lt + rk;
                kidx[row * KNN + p] = base + tid;
                kval[row * KNN + p] = evstar;
            }
        }
        run_lt += tg;
        run_eq += te;
        __syncthreads();
    }
    red[tid] = gsum;
    __syncthreads();
    for (int s = 128; s > 0; s >>= 1) {
        if (tid < s) red[tid] += red[tid + s];
        __syncthreads();
    }
    if (tid == 0) deg[row] = red[0] + (float)rem * evstar;
}

__global__ void buildL_k(const int* __restrict__ kidx, const float* __restrict__ kval,
                         const float* __restrict__ deg, float* __restrict__ lval) {
    int e = blockIdx.x * blockDim.x + threadIdx.x;
    if (e >= NPTS * KNN) return;
    int i = e / KNN;
    int j = kidx[e];
    float di = 1.f / sqrtf(deg[i]);
    float dj = 1.f / sqrtf(deg[j]);
    lval[e] = -kval[e] * di * dj;
}

__global__ void spmm_k(const int* __restrict__ kidx, const float* __restrict__ lval,
                       const float* __restrict__ T, const float* __restrict__ P,
                       float* __restrict__ Y, int F, int mode) {
    __shared__ int sidx[KNN];
    __shared__ float sval[KNN];
    int row = blockIdx.x;
    if (threadIdx.x < KNN) {
        sidx[threadIdx.x] = kidx[row * KNN + threadIdx.x];
        sval[threadIdx.x] = lval[row * KNN + threadIdx.x];
    }
    __syncthreads();
    for (int f = threadIdx.x; f < F; f += blockDim.x) {
        float acc = T[(size_t)row * F + f];
#pragma unroll 8
        for (int t = 0; t < KNN; t++) acc = fmaf(sval[t], T[(size_t)sidx[t] * F + f], acc);
        if (mode == 1) acc = 2.f * acc - P[(size_t)row * F + f];
        Y[(size_t)row * F + f] = acc;
    }
}

// cheb spmm with bf16 GATHER (reads neighbor rows from the bf16 snapshot, halving
// gather traffic); own row + P stay fp32; fp32 accumulation; dual fp32+bf16 output.
__global__ void spmm4h_k(const int* __restrict__ kidx, const float* __restrict__ lval,
                         const float4* __restrict__ T, const __nv_bfloat16* __restrict__ Tbf,
                         const float4* __restrict__ P,
                         float4* __restrict__ Y, __nv_bfloat16* __restrict__ Ybf, int mode) {
    __shared__ int sidx[KNN];
    __shared__ float sval[KNN];
    const int F4 = CH / 4;
    int row = blockIdx.x;
    if (threadIdx.x < KNN) {
        sidx[threadIdx.x] = kidx[row * KNN + threadIdx.x];
        sval[threadIdx.x] = lval[row * KNN + threadIdx.x];
    }
    __syncthreads();
    for (int f = threadIdx.x; f < F4; f += blockDim.x) {
        float4 a = T[(size_t)row * F4 + f];
#pragma unroll 8
        for (int t = 0; t < KNN; t++) {
            const __nv_bfloat162* g =
                (const __nv_bfloat162*)(Tbf + (size_t)sidx[t] * KPAD + 4 * f);
            __nv_bfloat162 v01 = g[0], v23 = g[1];
            float2 f01 = __bfloat1622float2(v01);
            float2 f23 = __bfloat1622float2(v23);
            float s = sval[t];
            a.x = fmaf(s, f01.x, a.x);
            a.y = fmaf(s, f01.y, a.y);
            a.z = fmaf(s, f23.x, a.z);
            a.w = fmaf(s, f23.y, a.w);
        }
        if (mode == 1) {
            float4 p = P[(size_t)row * F4 + f];
            a.x = 2.f * a.x - p.x;
            a.y = 2.f * a.y - p.y;
            a.z = 2.f * a.z - p.z;
            a.w = 2.f * a.w - p.w;
        }
        Y[(size_t)row * F4 + f] = a;
        __nv_bfloat162* d2 = (__nv_bfloat162*)(Ybf + (size_t)row * KPAD + 4 * f);
        d2[0] = __floats2bfloat162_rn(a.x, a.y);
        d2[1] = __floats2bfloat162_rn(a.z, a.w);
    }
}

__global__ void pack3_k(const float* __restrict__ A, const float* __restrict__ B,
                        const float* __restrict__ C, float* __restrict__ Y, int M, int F) {
    int i = blockIdx.x * blockDim.x + threadIdx.x;
    if (i >= M * F) return;
    int r = i / F, f = i % F;
    size_t o = (size_t)r * 3 * F + f;
    Y[o] = A[i];
    Y[o + F] = B[i];
    Y[o + 2 * F] = C[i];
}

// split-K regmat stage 1
__global__ void regmat1_k(const float* __restrict__ O, const float* __restrict__ Tf,
                          float* __restrict__ part) {
    __shared__ float sT[128][FIN];
    int c = blockIdx.x * 128 + threadIdx.x;
    int n0 = blockIdx.y * 128;
    for (int i = threadIdx.x; i < 128 * FIN; i += 128) sT[i / FIN][i % FIN] = Tf[(n0 + i / FIN) * FIN + i % FIN];
    __syncthreads();
    float a[FIN] = {0, 0, 0, 0, 0, 0};
    if (c < CH) {
        for (int n = 0; n < 128; n++) {
            float o = O[(size_t)(n0 + n) * CH + c];
#pragma unroll
            for (int f = 0; f < FIN; f++) a[f] = fmaf(o, sT[n][f], a[f]);
        }
#pragma unroll
        for (int f = 0; f < FIN; f++) part[((size_t)blockIdx.y * CH + c) * FIN + f] = a[f];
    }
}

__global__ void regmat2_k(const float* __restrict__ part, float* __restrict__ Mo) {
    int i = blockIdx.x * 256 + threadIdx.x;
    if (i >= CH * FIN) return;
    float s = 0.f;
    for (int k = 0; k < 32; k++) s += part[(size_t)k * CH * FIN + i];
    Mo[i] = s;
}

__global__ void fro_k(const float* __restrict__ v, int n, float* __restrict__ dst) {
    __shared__ float red[256];
    float s = 0.f;
    for (int i = threadIdx.x; i < n; i += 256) { float x = v[i]; s += x * x; }
    red[threadIdx.x] = s;
    __syncthreads();
    for (int st = 128; st > 0; st >>= 1) {
        if (threadIdx.x < st) red[threadIdx.x] += red[threadIdx.x + st];
        __syncthreads();
    }
    if (threadIdx.x == 0) dst[0] = sqrtf(red[0]);
}

__global__ void reebpool_k(const float* __restrict__ O, const int* __restrict__ sccs,
                           float* __restrict__ vfr) {
    __shared__ int sidx[SCC];
    int r = blockIdx.x;
    for (int i = threadIdx.x; i < SCC; i += blockDim.x) sidx[i] = sccs[r * SCC + i];
    __syncthreads();
    int c = blockIdx.y * 256 + threadIdx.x;
    if (c >= CH) return;
    float m = -FLT_MAX;
    for (int s = 0; s < SCC; s++) m = fmaxf(m, O[(size_t)sidx[s] * CH + c]);
    vfr[r * CH + c] = m;
}

// fused Reeb Chebyshev prep: per column c compute T1 = Lr@vfr, T2 = 2Lr@T1 - vfr,
// write packed xhr = [vfr | T1 | T2].
__global__ void reebfuse_k(const float* __restrict__ Lr, const float* __restrict__ vfr,
                           float* __restrict__ xhr) {
    __shared__ float sL[NRB * NRB];
    for (int i = threadIdx.x; i < NRB * NRB; i += blockDim.x) sL[i] = Lr[i];
    __syncthreads();
    int c = blockIdx.x * blockDim.x + threadIdx.x;
    if (c >= CH) return;
    float v0[NRB], t1[NRB];
#pragma unroll
    for (int q = 0; q < NRB; q++) v0[q] = vfr[q * CH + c];
#pragma unroll
    for (int r = 0; r < NRB; r++) {
        float a = 0.f;
#pragma unroll
        for (int q = 0; q < NRB; q++) a = fmaf(sL[r * NRB + q], v0[q], a);
        t1[r] = a;
    }
#pragma unroll
    for (int r = 0; r < NRB; r++) {
        float a = 0.f;
#pragma unroll
        for (int q = 0; q < NRB; q++) a = fmaf(sL[r * NRB + q], t1[q], a);
        float t2 = 2.f * a - v0[r];
        xhr[(size_t)r * 3 * CH + c] = v0[r];
        xhr[(size_t)r * 3 * CH + CH + c] = t1[r];
        xhr[(size_t)r * 3 * CH + 2 * CH + c] = t2;
    }
}

__global__ void colmax1_k(const float* __restrict__ X, float* __restrict__ part) {
    int c = blockIdx.x * 256 + threadIdx.x;
    if (c >= CH) return;
    int r0 = blockIdx.y * 128;
    float m = -FLT_MAX;
    for (int r = r0; r < r0 + 128; r++) m = fmaxf(m, X[(size_t)r * CH + c]);
    part[(size_t)blockIdx.y * CH + c] = m;
}

__global__ void colmax2_k(const float* __restrict__ part, float* __restrict__ y) {
    int c = blockIdx.x * 256 + threadIdx.x;
    if (c >= CH) return;
    float m = -FLT_MAX;
    for (int k = 0; k < 32; k++) m = fmaxf(m, part[(size_t)k * CH + c]);
    y[c] = m;
}

__global__ void colmax_k(const float* __restrict__ X, int M, int N, float* __restrict__ y) {
    int c = blockIdx.x * blockDim.x + threadIdx.x;
    if (c >= N) return;
    float m = -FLT_MAX;
    for (int r = 0; r < M; r++) m = fmaxf(m, X[(size_t)r * N + c]);
    y[c] = m;
}

__global__ void fc1a_k(const float* __restrict__ v, const float* __restrict__ W,
                       float* __restrict__ part) {
    int j = blockIdx.x * 128 + threadIdx.x;
    int i0 = blockIdx.y * 125;
    float acc = 0.f;
    for (int i = i0; i < i0 + 125; i++) acc = fmaf(v[i], W[(size_t)i * 512 + j], acc);
    part[(size_t)blockIdx.y * 512 + j] = acc;
}

__global__ void fc1b_k(const float* __restrict__ part, const float* __restrict__ b,
                       float* __restrict__ y) {
    int j = blockIdx.x * 128 + threadIdx.x;
    float acc = b[j];
    for (int k = 0; k < 16; k++) acc += part[(size_t)k * 512 + j];
    y[j] = fmaxf(acc, 0.f);
}

__global__ void fc_k(const float* __restrict__ v, const float* __restrict__ W,
                     const float* __restrict__ b, float* __restrict__ y,
                     int In, int Out, int relu) {
    int j = blockIdx.x * blockDim.x + threadIdx.x;
    if (j >= Out) return;
    float acc = b[j];
    for (int i = 0; i < In; i++) acc = fmaf(v[i], W[(size_t)i * Out + j], acc);
    if (relu) acc = fmaxf(acc, 0.f);
    y[j] = acc;
}

__global__ void wregs_k(const float* __restrict__ w1, const float* __restrict__ b1,
                        const float* __restrict__ w2, const float* __restrict__ b2,
                        const float* __restrict__ w3, const float* __restrict__ b3,
                        float* __restrict__ dst) {
    __shared__ float red[256];
    float s = 0.f;
    for (int i = threadIdx.x; i < 2000; i += 256) { float v = w1[(size_t)i * 512]; s += v * v; }
    red[threadIdx.x] = s;
    __syncthreads();
    for (int st = 128; st > 0; st >>= 1) {
        if (threadIdx.x < st) red[threadIdx.x] += red[threadIdx.x + st];
        __syncthreads();
    }
    if (threadIdx.x == 0) dst[2] = red[0];
    __syncthreads();
    s = 0.f;
    for (int i = threadIdx.x; i < 512; i += 256) { float v = w2[(size_t)i * 128]; s += v * v; }
    red[threadIdx.x] = s;
    __syncthreads();
    for (int st = 128; st > 0; st >>= 1) {
        if (threadIdx.x < st) red[threadIdx.x] += red[threadIdx.x + st];
        __syncthreads();
    }
    if (threadIdx.x == 0) dst[4] = red[0];
    __syncthreads();
    s = 0.f;
    for (int i = threadIdx.x; i < 128; i += 256) { float v = w3[(size_t)i * 40]; s += v * v; }
    red[threadIdx.x] = s;
    __syncthreads();
    for (int st = 128; st > 0; st >>= 1) {
        if (threadIdx.x < st) red[threadIdx.x] += red[threadIdx.x + st];
        __syncthreads();
    }
    if (threadIdx.x == 0) {
        dst[6] = red[0];
        dst[3] = b1[0] * b1[0];
        dst[5] = b2[0] * b2[0];
        dst[7] = b3[0] * b3[0];
    }
}

// ---------------- host launch ----------------
extern "C" void kernel_launch(void* const* d_in, const int* in_sizes, int n_in,
                              void* d_out, int out_size) {
    const float* x    = (const float*)d_in[0];
    const float* Lr   = (const float*)d_in[5];
    const int*   sccs = (const int*)d_in[6];
    const float* W1   = (const float*)d_in[7];
    const float* b1   = (const float*)d_in[8];
    const float* W2   = (const float*)d_in[9];
    const float* b2   = (const float*)d_in[10];
    const float* Wr   = (const float*)d_in[11];
    const float* br   = (const float*)d_in[12];
    const float* f1w  = (const float*)d_in[13];
    const float* f1b  = (const float*)d_in[14];
    const float* f2w  = (const float*)d_in[15];
    const float* f2b  = (const float*)d_in[16];
    const float* f3w  = (const float*)d_in[17];
    const float* f3b  = (const float*)d_in[18];
    float* out = (float*)d_out;

    float *adj, *sq, *kval, *deg, *lval, *o1, *ta, *tb, *accb, *t1a, *t2a, *xh1;
    float *l2x, *Mb, *vfr, *xhr, *reeb, *of, *fc1o, *fc2o, *part;
    int* kidx;
    __nv_bfloat16 *tbf, *o1l, *w2t;
    cudaGetSymbolAddress((void**)&adj, g_adj);
    cudaGetSymbolAddress((void**)&sq, g_sq);
    cudaGetSymbolAddress((void**)&kidx, g_kidx);
    cudaGetSymbolAddress((void**)&kval, g_kval);
    cudaGetSymbolAddress((void**)&deg, g_deg);
    cudaGetSymbolAddress((void**)&lval, g_lval);
    cudaGetSymbolAddress((void**)&o1, g_o1);
    cudaGetSymbolAddress((void**)&ta, g_ta);
    cudaGetSymbolAddress((void**)&tb, g_tb);
    cudaGetSymbolAddress((void**)&accb, g_accb);
    cudaGetSymbolAddress((void**)&t1a, g_t1a);
    cudaGetSymbolAddress((void**)&t2a, g_t2a);
    cudaGetSymbolAddress((void**)&xh1, g_xh1);
    cudaGetSymbolAddress((void**)&l2x, g_l2x);
    cudaGetSymbolAddress((void**)&Mb, g_Mb);
    cudaGetSymbolAddress((void**)&vfr, g_vfr);
    cudaGetSymbolAddress((void**)&xhr, g_xhr);
    cudaGetSymbolAddress((void**)&reeb, g_reeb);
    cudaGetSymbolAddress((void**)&of, g_of);
    cudaGetSymbolAddress((void**)&fc1o, g_fc1);
    cudaGetSymbolAddress((void**)&fc2o, g_fc2);
    cudaGetSymbolAddress((void**)&part, g_part);
    cudaGetSymbolAddress((void**)&tbf, g_tbf);
    cudaGetSymbolAddress((void**)&o1l, g_o1l);
    cudaGetSymbolAddress((void**)&w2t, g_w2t);

    const int BF_SMEM = 2 * 2 * 128 * 72 * 2;   // 73728 B
    cudaFuncSetAttribute(bfmma_k<0>, cudaFuncAttributeMaxDynamicSharedMemorySize, BF_SMEM);
    cudaFuncSetAttribute(bfmma_k<1>, cudaFuncAttributeMaxDynamicSharedMemorySize, BF_SMEM);

    dim3 gBig(32, 32);
    dim3 gC1(8, 32);
    dim3 gRb(8, 1);
    const size_t SLOT = (size_t)NPTS * KPAD;

    // ---- graph 1 (exact fp32; d^2 full grid coalesced, exp deferred to topk) ----
    rowsq_k<<<NPTS, 128>>>(x, sq, FIN);
    sgemm_k<1, 2><<<gBig, 256>>>(x, x, adj, NPTS, NPTS, FIN, sq);
    topkr_k<<<NPTS, 256>>>(adj, kidx, kval, deg);
    buildL_k<<<(NPTS * KNN + 255) / 256, 256>>>(kidx, kval, deg, lval);

    // ---- cheb conv 1 (exact fp32, fused bias+relu) ----
    spmm_k<<<NPTS, 64>>>(kidx, lval, x, (const float*)0, t1a, FIN, 0);
    spmm_k<<<NPTS, 64>>>(kidx, lval, t1a, x, t2a, FIN, 1);
    pack3_k<<<(NPTS * FIN + 255) / 256, 256>>>(x, t1a, t2a, xh1, NPTS, FIN);
    sgemm_k<0, 3><<<gC1, 256>>>(xh1, W1, o1, NPTS, CH, 3 * FIN, b1);

    // ---- reg1 (split-K) ----
    regmat1_k<<<dim3(8, 32), 128>>>(o1, t1a, part);
    regmat2_k<<<(CH * FIN + 255) / 256, 256>>>(part, Mb);
    if (out_size >= 48) fro_k<<<1, 256>>>(Mb, CH * FIN, out + 40);

    reebpool_k<<<dim3(NRB, 4), 256>>>(o1, sccs, vfr);

    // ---- graph 2 (bf16 mma, split hi/lo; d^2 epilogue, exp deferred) ----
    splitsq_k<<<NPTS, 256>>>(o1, tbf, o1l, sq);
    w2t_k<<<dim3(32, 32, 6), dim3(32, 32)>>>(W2, w2t);
    {
        BfSegs s;
        s.a[0] = tbf;  s.b[0] = tbf;   // hi.hi^T
        s.a[1] = tbf;  s.b[1] = o1l;   // hi.lo^T
        s.a[2] = o1l;  s.b[2] = tbf;   // lo.hi^T
        s.a[3] = s.a[4] = s.a[5] = tbf;
        s.b[3] = s.b[4] = s.b[5] = tbf;
        bfmma_k<1><<<gBig, 256, BF_SMEM>>>(s, 3, KPAD, KPAD, sq, adj, NPTS, NPTS);
    }
    topkr_k<<<NPTS, 256>>>(adj, kidx, kval, deg);
    buildL_k<<<(NPTS * KNN + 255) / 256, 256>>>(kidx, kval, deg, lval);

    // ---- Chebyshev recursion (fp32 own-row/accum, bf16 gather) + bf16 snapshots ----
    spmm4h_k<<<NPTS, 256>>>(kidx, lval, (const float4*)o1, tbf, (const float4*)0,
                            (float4*)ta, tbf + 1 * SLOT, 0);
    spmm4h_k<<<NPTS, 256>>>(kidx, lval, (const float4*)ta, tbf + 1 * SLOT, (const float4*)o1,
                            (float4*)tb, tbf + 2 * SLOT, 1);
    spmm4h_k<<<NPTS, 256>>>(kidx, lval, (const float4*)tb, tbf + 2 * SLOT, (const float4*)ta,
                            (float4*)o1, tbf + 3 * SLOT, 1);
    spmm4h_k<<<NPTS, 256>>>(kidx, lval, (const float4*)o1, tbf + 3 * SLOT, (const float4*)tb,
                            (float4*)ta, tbf + 4 * SLOT, 1);
    spmm4h_k<<<NPTS, 256>>>(kidx, lval, (const float4*)ta, tbf + 4 * SLOT, (const float4*)o1,
                            (float4*)tb, tbf + 5 * SLOT, 1);

    // ---- fused cheb conv 2 ----
    {
        BfSegs s;
        for (int i = 0; i < 6; i++) {
            s.a[i] = tbf + (size_t)i * SLOT;
            s.b[i] = w2t + (size_t)i * KPAD * KPAD;
        }
        bfmma_k<0><<<gC1, 256, BF_SMEM>>>(s, 6, KPAD, KPAD, b2, accb, CH, CH);
    }

    // ---- reg2 (split-K) ----
    spmm_k<<<NPTS, 64>>>(kidx, lval, x, (const float*)0, l2x, FIN, 0);
    regmat1_k<<<dim3(8, 32), 128>>>(accb, l2x, part);
    regmat2_k<<<(CH * FIN + 255) / 256, 256>>>(part, Mb);
    if (out_size >= 48) fro_k<<<1, 256>>>(Mb, CH * FIN, out + 41);

    // ---- Reeb branch (exact fp32, fused) ----
    reebfuse_k<<<(CH + 255) / 256, 256>>>(Lr, vfr, xhr);
    sgemm_k<0, 3><<<gRb, 256>>>(xhr, Wr, reeb, NRB, CH, 3 * CH, br);

    // ---- head ----
    colmax_k<<<(CH + 255) / 256, 256>>>(reeb, NRB, CH, of);
    colmax1_k<<<dim3(4, 32), 256>>>(accb, part);
    colmax2_k<<<4, 256>>>(part, of + CH);
    fc1a_k<<<dim3(4, 16), 128>>>(of, f1w, part);
    fc1b_k<<<4, 128>>>(part, f1b, fc1o);
    fc_k<<<1, 128>>>(fc1o, f2w, f2b, fc2o, 512, 128, 1);
    fc_k<<<1, 64>>>(fc2o, f3w, f3b, out, 128, 40, 0);

    if (out_size >= 48) wregs_k<<<1, 256>>>(f1w, f1b, f2w, f2b, f3w, f3b, out + 40);
}